// round 9
// baseline (speedup 1.0000x reference)
#include <cuda_runtime.h>
#include <cuda_bf16.h>
#include <cstdint>

// Problem constants
#define B_SZ  512
#define ZI    16
#define T_SZ  8
#define D     128
#define MROWS (B_SZ * ZI)   // 8192 img rows
#define NROWS (B_SZ * T_SZ) // 4096 text rows

// GEMM tiling: block computes 128x(128*TPB), warp tile 32x64 per subtile
#define BM    128
#define BN    128
#define TPB   4             // B tiles per block (A reused)
#define LDS8  144           // padded fp8 row stride in bytes (conflict-free)
#define GEMM_THREADS 256
#define NBX   (NROWS / BN)  // 32
#define NBY   (MROWS / BM)  // 64

// dynamic smem layout (bytes)
#define TILE_BYTES (BM * LDS8)                  // 18432
#define SMEM_A     0
#define SMEM_B0    TILE_BYTES                   // B double buffer
#define SMEM_EBUF  (TILE_BYTES * 3)             // 55296
#define SMEM_TOTAL (SMEM_EBUF + 4 * 128 * 4)    // 57344

// -------- device scratch (no allocations; zero-initialized) --------
__device__ uint4 g_imgn8[MROWS * D / 16];    // normalized img, e4m3, 1 MB
__device__ uint4 g_textn8[NROWS * D / 16];   // normalized text, e4m3, 0.5 MB
__device__ float g_part_i2t[B_SZ * 64];      // [bi][bx*2+wc] partial exp-sums
__device__ float g_part_t2i[NROWS * NBY];    // [col][by] partial exp-sums (transposed)
__device__ float g_mdiag[B_SZ * T_SZ];       // M[bi,bi,t]
__device__ float g_blockpart[B_SZ / 8];      // per-block loss partials (64)
__device__ unsigned int g_ticket;            // completion counter for reduce kernel

// ============================================================
// Kernel 1: L2 normalize rows of 128 f32 -> e4m3; 2 rows per warp
// ============================================================
__global__ void normalize_kernel(const float* __restrict__ img,
                                 const float* __restrict__ text) {
    int gw   = (blockIdx.x * blockDim.x + threadIdx.x) >> 5;  // warp id
    int lane = threadIdx.x & 31;
    int r0 = gw * 2;                       // rows r0, r0+1 (never straddle tensors)
    const float* src;
    uint32_t* dst;
    int lrow;
    if (r0 < MROWS) { src = img;  lrow = r0;         dst = reinterpret_cast<uint32_t*>(g_imgn8); }
    else            { src = text; lrow = r0 - MROWS; dst = reinterpret_cast<uint32_t*>(g_textn8); }
    const float4 v0 = reinterpret_cast<const float4*>(src)[lrow * 32 + lane];
    const float4 v1 = reinterpret_cast<const float4*>(src)[(lrow + 1) * 32 + lane];
    float s0 = v0.x * v0.x + v0.y * v0.y + v0.z * v0.z + v0.w * v0.w;
    float s1 = v1.x * v1.x + v1.y * v1.y + v1.z * v1.z + v1.w * v1.w;
#pragma unroll
    for (int s = 16; s > 0; s >>= 1) {
        s0 += __shfl_xor_sync(0xffffffffu, s0, s);
        s1 += __shfl_xor_sync(0xffffffffu, s1, s);
    }
    float i0 = rsqrtf(fmaxf(s0, 1e-24f));
    float i1 = rsqrtf(fmaxf(s1, 1e-24f));
    uint32_t p0, p1;
    asm("{ .reg .b16 lo, hi;\n\t"
        "cvt.rn.satfinite.e4m3x2.f32 lo, %2, %1;\n\t"
        "cvt.rn.satfinite.e4m3x2.f32 hi, %4, %3;\n\t"
        "mov.b32 %0, {lo, hi}; }"
        : "=r"(p0) : "f"(v0.x * i0), "f"(v0.y * i0), "f"(v0.z * i0), "f"(v0.w * i0));
    asm("{ .reg .b16 lo, hi;\n\t"
        "cvt.rn.satfinite.e4m3x2.f32 lo, %2, %1;\n\t"
        "cvt.rn.satfinite.e4m3x2.f32 hi, %4, %3;\n\t"
        "mov.b32 %0, {lo, hi}; }"
        : "=r"(p1) : "f"(v1.x * i1), "f"(v1.y * i1), "f"(v1.z * i1), "f"(v1.w * i1));
    dst[lrow * 32 + lane]       = p0;
    dst[(lrow + 1) * 32 + lane] = p1;
}

// ============================================================
// Kernel 2: fp8 GEMM, 4 N-tiles per block, cp.async double-buffered B
// ============================================================
extern __shared__ char smem_raw[];

__device__ __forceinline__ void mma_fp8(float* c, const uint32_t* a, uint32_t b0, uint32_t b1) {
    asm volatile(
        "mma.sync.aligned.m16n8k32.row.col.f32.e4m3.e4m3.f32 "
        "{%0,%1,%2,%3}, {%4,%5,%6,%7}, {%8,%9}, {%0,%1,%2,%3};\n"
        : "+f"(c[0]), "+f"(c[1]), "+f"(c[2]), "+f"(c[3])
        : "r"(a[0]), "r"(a[1]), "r"(a[2]), "r"(a[3]), "r"(b0), "r"(b1));
}

__device__ __forceinline__ void cpa16(uint32_t s, const void* g) {
    asm volatile("cp.async.cg.shared.global [%0], [%1], 16;\n" :: "r"(s), "l"(g));
}

__global__ void __launch_bounds__(GEMM_THREADS, 2)
gemm_kernel() {
    float* ebuf = reinterpret_cast<float*>(smem_raw + SMEM_EBUF);  // [4][128]

    const int bx0 = blockIdx.x * TPB, by = blockIdx.y;
    const int tid = threadIdx.x;
    const int w = tid >> 5, lane = tid & 31;
    const int wr = w >> 1, wc = w & 1;

    uint32_t sbase = (uint32_t)__cvta_generic_to_shared(smem_raw);
    const uint32_t sA = sbase + SMEM_A;
    const uint32_t sB0 = sbase + SMEM_B0;

    // ---- prologue: cp.async A tile + B tile 0 ----
    {
        const uint4* gA = g_imgn8 + (size_t)by * BM * (D / 16);
        const uint4* gB = g_textn8 + (size_t)bx0 * BN * (D / 16);
#pragma unroll
        for (int i = 0; i < 4; i++) {
            int idx = tid + i * GEMM_THREADS;          // 0..1023
            int r = idx >> 3, c = idx & 7;
            cpa16(sA + r * LDS8 + c * 16, gA + idx);
            cpa16(sB0 + r * LDS8 + c * 16, gB + idx);
        }
        asm volatile("cp.async.commit_group;\n");
        asm volatile("cp.async.wait_group 0;\n");
    }
    __syncthreads();

    // ---- per-thread relative ldmatrix addresses ----
    uint32_t aAddr[2], bRel[4];
#pragma unroll
    for (int mt = 0; mt < 2; mt++)
        aAddr[mt] = sA + (wr * 32 + mt * 16 + (lane & 15)) * LDS8 + ((lane & 16) ? 16 : 0);
#pragma unroll
    for (int p = 0; p < 4; p++)
        bRel[p] = (wc * 64 + p * 16 + (lane & 7) + ((lane & 16) ? 8 : 0)) * LDS8 + ((lane & 8) ? 16 : 0);

    // ---- loop over 4 B tiles ----
    for (int j = 0; j < TPB; j++) {
        const int bx = bx0 + j;
        const uint32_t sBj = sB0 + (uint32_t)(j & 1) * TILE_BYTES;

        // prefetch next B tile into the other buffer
        if (j + 1 < TPB) {
            const uint4* gB = g_textn8 + (size_t)(bx + 1) * BN * (D / 16);
            const uint32_t sBn = sB0 + (uint32_t)((j + 1) & 1) * TILE_BYTES;
#pragma unroll
            for (int i = 0; i < 4; i++) {
                int idx = tid + i * GEMM_THREADS;
                int r = idx >> 3, c = idx & 7;
                cpa16(sBn + r * LDS8 + c * 16, gB + idx);
            }
            asm volatile("cp.async.commit_group;\n");
        }

        float acc[2][8][4];
#pragma unroll
        for (int mt = 0; mt < 2; mt++)
#pragma unroll
            for (int nt = 0; nt < 8; nt++)
#pragma unroll
                for (int q = 0; q < 4; q++) acc[mt][nt][q] = 0.0f;

        // ---- mainloop: 4 k-steps of 32 ----
#pragma unroll
        for (int ks = 0; ks < 4; ks++) {
            uint32_t a[2][4];
#pragma unroll
            for (int mt = 0; mt < 2; mt++)
                asm volatile("ldmatrix.sync.aligned.m8n8.x4.shared.b16 {%0,%1,%2,%3}, [%4];\n"
                             : "=r"(a[mt][0]), "=r"(a[mt][1]), "=r"(a[mt][2]), "=r"(a[mt][3])
                             : "r"(aAddr[mt] + ks * 32));
            uint32_t b[4][4];
#pragma unroll
            for (int p = 0; p < 4; p++)
                asm volatile("ldmatrix.sync.aligned.m8n8.x4.shared.b16 {%0,%1,%2,%3}, [%4];\n"
                             : "=r"(b[p][0]), "=r"(b[p][1]), "=r"(b[p][2]), "=r"(b[p][3])
                             : "r"(sBj + bRel[p] + ks * 32));
#pragma unroll
            for (int mt = 0; mt < 2; mt++)
#pragma unroll
                for (int nt = 0; nt < 8; nt++)
                    mma_fp8(acc[mt][nt], a[mt], b[nt >> 1][(nt & 1) * 2], b[nt >> 1][(nt & 1) * 2 + 1]);
        }

        // ---- epilogue for this tile ----
        float cs0 = 0.0f, cs1 = 0.0f;
#pragma unroll
        for (int mt = 0; mt < 2; mt++) {
            const int bi = by * 8 + wr * 2 + mt;
            float M0s[8], M1s[8];
#pragma unroll
            for (int nt = 0; nt < 8; nt++) {
                float m0 = fmaxf(acc[mt][nt][0], acc[mt][nt][2]);
                float m1 = fmaxf(acc[mt][nt][1], acc[mt][nt][3]);
#pragma unroll
                for (int s = 4; s < 32; s <<= 1) {
                    m0 = fmaxf(m0, __shfl_xor_sync(0xffffffffu, m0, s));
                    m1 = fmaxf(m1, __shfl_xor_sync(0xffffffffu, m1, s));
                }
                M0s[nt] = m0; M1s[nt] = m1;
            }
            // redistribute: lane L takes (nt = L>>2, class = L&3) -> cols 2L, 2L+1
            float m0v = 0.0f, m1v = 0.0f;
#pragma unroll
            for (int nt = 0; nt < 8; nt++) {
                float t0 = __shfl_sync(0xffffffffu, M0s[nt], lane & 3);
                float t1 = __shfl_sync(0xffffffffu, M1s[nt], lane & 3);
                if ((lane >> 2) == nt) { m0v = t0; m1v = t1; }
            }
            float e0 = __expf(m0v), e1 = __expf(m1v);
            cs0 += e0; cs1 += e1;
            float ls = e0 + e1;
#pragma unroll
            for (int s = 1; s < 32; s <<= 1) ls += __shfl_xor_sync(0xffffffffu, ls, s);
            if (lane == 0) g_part_i2t[bi * 64 + bx * 2 + wc] = ls;   // unique writer
            int gc = bx * 128 + wc * 64 + 2 * lane;
            if ((gc >> 3) == bi) {
                g_mdiag[bi * 8 + (gc & 7)]       = m0v;
                g_mdiag[bi * 8 + ((gc + 1) & 7)] = m1v;
            }
        }
        *reinterpret_cast<float2*>(&ebuf[wr * 128 + wc * 64 + 2 * lane]) = make_float2(cs0, cs1);
        __syncthreads();
        if (tid < 128) {
            float s = ebuf[tid] + ebuf[128 + tid] + ebuf[256 + tid] + ebuf[384 + tid];
            g_part_t2i[(bx * 128 + tid) * NBY + by] = s;             // unique writer
        }
        // ensure next B tile landed and ebuf consumed before next iteration
        if (j + 1 < TPB) asm volatile("cp.async.wait_group 0;\n");
        __syncthreads();
    }
}

// ============================================================
// Kernel 3: per-bi loss + ticket-gated final sum
// ============================================================
__global__ void reduce_kernel(float* __restrict__ out) {
    __shared__ float red[8];
    __shared__ int is_last;
    int w = threadIdx.x >> 5, lane = threadIdx.x & 31;
    int bi = blockIdx.x * 8 + w;
    int t = lane >> 2, q = lane & 3;
    const float4* p = reinterpret_cast<const float4*>(&g_part_t2i[(bi * 8 + t) * NBY + q * 16]);
    float4 x0 = p[0], x1 = p[1], x2 = p[2], x3 = p[3];
    float s = ((x0.x + x0.y) + (x0.z + x0.w)) + ((x1.x + x1.y) + (x1.z + x1.w))
            + ((x2.x + x2.y) + (x2.z + x2.w)) + ((x3.x + x3.y) + (x3.z + x3.w));
    s += __shfl_xor_sync(0xffffffffu, s, 1);
    s += __shfl_xor_sync(0xffffffffu, s, 2);
    float v = (q == 0) ? __logf(s) : 0.0f;
    float2 di2 = reinterpret_cast<const float2*>(&g_part_i2t[bi * 64])[lane];
    float den = di2.x + di2.y;
    float md = (lane < 8) ? g_mdiag[bi * 8 + lane] : 0.0f;
#pragma unroll
    for (int sh = 1; sh < 32; sh <<= 1) {
        v   += __shfl_xor_sync(0xffffffffu, v, sh);
        den += __shfl_xor_sync(0xffffffffu, den, sh);
        md  += __shfl_xor_sync(0xffffffffu, md, sh);
    }
    if (lane == 0) red[w] = __logf(den) + v - 1.125f * md;
    __syncthreads();
    if (threadIdx.x == 0) {
        float c = 0.0f;
#pragma unroll
        for (int i = 0; i < 8; i++) c += red[i];
        g_blockpart[blockIdx.x] = c;
        __threadfence();
        unsigned int old = atomicAdd(&g_ticket, 1u);
        is_last = (old == 63u) ? 1 : 0;
    }
    __syncthreads();
    if (!is_last) return;
    if (threadIdx.x < 32) {
        __threadfence();
        float total = g_blockpart[threadIdx.x] + g_blockpart[threadIdx.x + 32];
#pragma unroll
        for (int sh = 16; sh > 0; sh >>= 1)
            total += __shfl_xor_sync(0xffffffffu, total, sh);
        if (threadIdx.x == 0) { out[0] = total; g_ticket = 0u; }
    }
}

// ============================================================
extern "C" void kernel_launch(void* const* d_in, const int* in_sizes, int n_in,
                              void* d_out, int out_size) {
    const float* img  = (const float*)d_in[0];   // (512,16,128) f32
    const float* text = (const float*)d_in[1];   // (512,8,128) f32
    float* out = (float*)d_out;

    cudaFuncSetAttribute(gemm_kernel, cudaFuncAttributeMaxDynamicSharedMemorySize, SMEM_TOTAL);

    normalize_kernel<<<(MROWS + NROWS) / 2 * 32 / 256, 256>>>(img, text);
    gemm_kernel<<<dim3(NBX / TPB, NBY), GEMM_THREADS, SMEM_TOTAL>>>();
    reduce_kernel<<<B_SZ / 8, 256>>>(out);
}

// round 10
// speedup vs baseline: 1.0981x; 1.0981x over previous
#include <cuda_runtime.h>
#include <cuda_bf16.h>
#include <cstdint>

// Problem constants
#define B_SZ  512
#define ZI    16
#define T_SZ  8
#define D     128
#define MROWS (B_SZ * ZI)   // 8192 img rows
#define NROWS (B_SZ * T_SZ) // 4096 text rows

// GEMM tiling: block computes 128x128, warp computes 32x64, fp8 k-step 32
#define BM    128
#define BN    128
#define LDS8  144           // padded fp8 row stride in bytes (conflict-free)
#define GEMM_THREADS 256
#define NBX   (NROWS / BN)  // 32
#define NBY   (MROWS / BM)  // 64

// dynamic smem layout (bytes)
#define SMEM_A     0
#define SMEM_B     (BM * LDS8)              // 18432
#define SMEM_EBUF  (SMEM_B + BN * LDS8)     // 36864
#define SMEM_TOTAL (SMEM_EBUF + 4 * 128 * 4)

// -------- device scratch (no allocations; zero-initialized) --------
__device__ uint4 g_imgn8[MROWS * D / 16];    // normalized img, e4m3, 1 MB
__device__ uint4 g_textn8[NROWS * D / 16];   // normalized text, e4m3, 0.5 MB
__device__ float g_part_i2t[B_SZ * 64];      // [bi][bx*2+wc] partial exp-sums
__device__ float g_part_t2i[NROWS * NBY];    // [col][by] partial exp-sums (transposed)
__device__ float g_mdiag[B_SZ * T_SZ];       // M[bi,bi,t]
__device__ float g_blockpart[B_SZ / 8];      // per-block loss partials (64)
__device__ unsigned int g_ticket;            // completion counter for reduce kernel

// ============================================================
// Kernel 1: L2 normalize rows of 128 f32 -> e4m3; 4 rows per warp
// (MLP=4: all loads in flight, 4 interleaved reduction chains)
// ============================================================
__global__ void normalize_kernel(const float* __restrict__ img,
                                 const float* __restrict__ text) {
    int gw   = (blockIdx.x * blockDim.x + threadIdx.x) >> 5;  // warp id
    int lane = threadIdx.x & 31;
    int r0 = gw * 4;                       // rows r0..r0+3 (never straddle tensors)
    const float* src;
    uint32_t* dst;
    int lrow;
    if (r0 < MROWS) { src = img;  lrow = r0;         dst = reinterpret_cast<uint32_t*>(g_imgn8); }
    else            { src = text; lrow = r0 - MROWS; dst = reinterpret_cast<uint32_t*>(g_textn8); }
    float4 v[4];
#pragma unroll
    for (int r = 0; r < 4; r++)
        v[r] = reinterpret_cast<const float4*>(src)[(lrow + r) * 32 + lane];
    float ss[4];
#pragma unroll
    for (int r = 0; r < 4; r++)
        ss[r] = v[r].x * v[r].x + v[r].y * v[r].y + v[r].z * v[r].z + v[r].w * v[r].w;
#pragma unroll
    for (int s = 16; s > 0; s >>= 1) {
#pragma unroll
        for (int r = 0; r < 4; r++)
            ss[r] += __shfl_xor_sync(0xffffffffu, ss[r], s);
    }
#pragma unroll
    for (int r = 0; r < 4; r++) {
        float inv = rsqrtf(fmaxf(ss[r], 1e-24f));
        uint32_t pack;
        asm("{ .reg .b16 lo, hi;\n\t"
            "cvt.rn.satfinite.e4m3x2.f32 lo, %2, %1;\n\t"
            "cvt.rn.satfinite.e4m3x2.f32 hi, %4, %3;\n\t"
            "mov.b32 %0, {lo, hi}; }"
            : "=r"(pack)
            : "f"(v[r].x * inv), "f"(v[r].y * inv), "f"(v[r].z * inv), "f"(v[r].w * inv));
        dst[(lrow + r) * 32 + lane] = pack;
    }
}

// ============================================================
// Kernel 2: fused fp8 GEMM + max_i + exp + partial reductions
// (exact R4 structure — known-good 43.4us path)
// ============================================================
extern __shared__ char smem_raw[];

__device__ __forceinline__ void mma_fp8(float* c, const uint32_t* a, uint32_t b0, uint32_t b1) {
    asm volatile(
        "mma.sync.aligned.m16n8k32.row.col.f32.e4m3.e4m3.f32 "
        "{%0,%1,%2,%3}, {%4,%5,%6,%7}, {%8,%9}, {%0,%1,%2,%3};\n"
        : "+f"(c[0]), "+f"(c[1]), "+f"(c[2]), "+f"(c[3])
        : "r"(a[0]), "r"(a[1]), "r"(a[2]), "r"(a[3]), "r"(b0), "r"(b1));
}

__global__ void __launch_bounds__(GEMM_THREADS, 2)
gemm_kernel() {
    char* As = smem_raw + SMEM_A;    // [128][144] fp8
    char* Bs = smem_raw + SMEM_B;    // [128][144] fp8
    float* ebuf = reinterpret_cast<float*>(smem_raw + SMEM_EBUF);  // [4][128]

    const int bx = blockIdx.x, by = blockIdx.y;
    const int tid = threadIdx.x;
    const int w = tid >> 5, lane = tid & 31;
    const int wr = w >> 1, wc = w & 1;

    // ---- load tiles (each 128x128 fp8 = 16KB) into padded smem ----
    {
        const uint4* gA = g_imgn8 + (size_t)by * BM * (D / 16);
        const uint4* gB = g_textn8 + (size_t)bx * BN * (D / 16);
#pragma unroll
        for (int i = 0; i < 4; i++) {
            int idx = tid + i * GEMM_THREADS;          // 0..1023
            int r = idx >> 3, c = idx & 7;
            *reinterpret_cast<uint4*>(As + r * LDS8 + c * 16) = gA[idx];
            *reinterpret_cast<uint4*>(Bs + r * LDS8 + c * 16) = gB[idx];
        }
    }
    __syncthreads();

    // ---- ldmatrix base addresses (fp8: k-half = 16 bytes) ----
    uint32_t sA = (uint32_t)__cvta_generic_to_shared(As);
    uint32_t sB = (uint32_t)__cvta_generic_to_shared(Bs);
    uint32_t aAddr[2], bAddr[4];
#pragma unroll
    for (int mt = 0; mt < 2; mt++)
        aAddr[mt] = sA + (wr * 32 + mt * 16 + (lane & 15)) * LDS8 + ((lane & 16) ? 16 : 0);
#pragma unroll
    for (int p = 0; p < 4; p++)
        bAddr[p] = sB + (wc * 64 + p * 16 + (lane & 7) + ((lane & 16) ? 8 : 0)) * LDS8 + ((lane & 8) ? 16 : 0);

    float acc[2][8][4];
#pragma unroll
    for (int mt = 0; mt < 2; mt++)
#pragma unroll
        for (int nt = 0; nt < 8; nt++)
#pragma unroll
            for (int j = 0; j < 4; j++) acc[mt][nt][j] = 0.0f;

    // ---- mainloop: 4 k-steps of 32 ----
#pragma unroll
    for (int ks = 0; ks < 4; ks++) {
        uint32_t a[2][4];
#pragma unroll
        for (int mt = 0; mt < 2; mt++)
            asm volatile("ldmatrix.sync.aligned.m8n8.x4.shared.b16 {%0,%1,%2,%3}, [%4];\n"
                         : "=r"(a[mt][0]), "=r"(a[mt][1]), "=r"(a[mt][2]), "=r"(a[mt][3])
                         : "r"(aAddr[mt] + ks * 32));
        uint32_t b[4][4];
#pragma unroll
        for (int p = 0; p < 4; p++)
            asm volatile("ldmatrix.sync.aligned.m8n8.x4.shared.b16 {%0,%1,%2,%3}, [%4];\n"
                         : "=r"(b[p][0]), "=r"(b[p][1]), "=r"(b[p][2]), "=r"(b[p][3])
                         : "r"(bAddr[p] + ks * 32));
#pragma unroll
        for (int mt = 0; mt < 2; mt++)
#pragma unroll
            for (int nt = 0; nt < 8; nt++)
                mma_fp8(acc[mt][nt], a[mt], b[nt >> 1][(nt & 1) * 2], b[nt >> 1][(nt & 1) * 2 + 1]);
    }

    // ---- epilogue ----
    float cs0 = 0.0f, cs1 = 0.0f;
#pragma unroll
    for (int mt = 0; mt < 2; mt++) {
        const int bi = by * 8 + wr * 2 + mt;
        float M0s[8], M1s[8];
#pragma unroll
        for (int nt = 0; nt < 8; nt++) {
            float m0 = fmaxf(acc[mt][nt][0], acc[mt][nt][2]);
            float m1 = fmaxf(acc[mt][nt][1], acc[mt][nt][3]);
#pragma unroll
            for (int s = 4; s < 32; s <<= 1) {
                m0 = fmaxf(m0, __shfl_xor_sync(0xffffffffu, m0, s));
                m1 = fmaxf(m1, __shfl_xor_sync(0xffffffffu, m1, s));
            }
            M0s[nt] = m0; M1s[nt] = m1;
        }
        // redistribute: lane L takes (nt = L>>2, class = L&3) -> cols 2L, 2L+1
        float m0v = 0.0f, m1v = 0.0f;
#pragma unroll
        for (int nt = 0; nt < 8; nt++) {
            float t0 = __shfl_sync(0xffffffffu, M0s[nt], lane & 3);
            float t1 = __shfl_sync(0xffffffffu, M1s[nt], lane & 3);
            if ((lane >> 2) == nt) { m0v = t0; m1v = t1; }
        }
        float e0 = __expf(m0v), e1 = __expf(m1v);
        cs0 += e0; cs1 += e1;
        // per-bi partial sum over this warp's 64 cols
        float ls = e0 + e1;
#pragma unroll
        for (int s = 1; s < 32; s <<= 1) ls += __shfl_xor_sync(0xffffffffu, ls, s);
        if (lane == 0) g_part_i2t[bi * 64 + bx * 2 + wc] = ls;   // unique writer
        // diagonal capture
        int gc = bx * 128 + wc * 64 + 2 * lane;
        if ((gc >> 3) == bi) {
            g_mdiag[bi * 8 + (gc & 7)]       = m0v;
            g_mdiag[bi * 8 + ((gc + 1) & 7)] = m1v;
        }
    }
    // per-column partial over this warp's 32 rows (2 bi groups) -> ebuf
    *reinterpret_cast<float2*>(&ebuf[wr * 128 + wc * 64 + 2 * lane]) = make_float2(cs0, cs1);
    __syncthreads();
    if (tid < 128) {
        float s = ebuf[tid] + ebuf[128 + tid] + ebuf[256 + tid] + ebuf[384 + tid];
        g_part_t2i[(bx * 128 + tid) * NBY + by] = s;             // unique writer
    }
}

// ============================================================
// Kernel 3: per-bi loss contribution. warp per bi, 8 warps/block.
// ============================================================
__global__ void reduce_bi_kernel() {
    __shared__ float red[8];
    int w = threadIdx.x >> 5, lane = threadIdx.x & 31;
    int bi = blockIdx.x * 8 + w;
    int t = lane >> 2, q = lane & 3;
    const float4* p = reinterpret_cast<const float4*>(&g_part_t2i[(bi * 8 + t) * NBY + q * 16]);
    float4 x0 = p[0], x1 = p[1], x2 = p[2], x3 = p[3];
    float s = ((x0.x + x0.y) + (x0.z + x0.w)) + ((x1.x + x1.y) + (x1.z + x1.w))
            + ((x2.x + x2.y) + (x2.z + x2.w)) + ((x3.x + x3.y) + (x3.z + x3.w));
    s += __shfl_xor_sync(0xffffffffu, s, 1);
    s += __shfl_xor_sync(0xffffffffu, s, 2);
    float v = (q == 0) ? __logf(s) : 0.0f;
    float2 di2 = reinterpret_cast<const float2*>(&g_part_i2t[bi * 64])[lane];
    float den = di2.x + di2.y;
    float md = (lane < 8) ? g_mdiag[bi * 8 + lane] : 0.0f;
#pragma unroll
    for (int sh = 1; sh < 32; sh <<= 1) {
        v   += __shfl_xor_sync(0xffffffffu, v, sh);
        den += __shfl_xor_sync(0xffffffffu, den, sh);
        md  += __shfl_xor_sync(0xffffffffu, md, sh);
    }
    if (lane == 0) red[w] = __logf(den) + v - 1.125f * md;
    __syncthreads();
    if (threadIdx.x == 0) {
        float c = 0.0f;
#pragma unroll
        for (int i = 0; i < 8; i++) c += red[i];
        g_blockpart[blockIdx.x] = c;
    }
}

// ============================================================
// Kernel 4: tiny final sum over 64 block partials
// ============================================================
__global__ void final_kernel(float* __restrict__ out) {
    int lane = threadIdx.x;
    float s = g_blockpart[lane] + g_blockpart[lane + 32];
#pragma unroll
    for (int sh = 16; sh > 0; sh >>= 1) s += __shfl_xor_sync(0xffffffffu, s, sh);
    if (lane == 0) out[0] = s;
}

// ============================================================
extern "C" void kernel_launch(void* const* d_in, const int* in_sizes, int n_in,
                              void* d_out, int out_size) {
    const float* img  = (const float*)d_in[0];   // (512,16,128) f32
    const float* text = (const float*)d_in[1];   // (512,8,128) f32
    float* out = (float*)d_out;

    cudaFuncSetAttribute(gemm_kernel, cudaFuncAttributeMaxDynamicSharedMemorySize, SMEM_TOTAL);

    normalize_kernel<<<(MROWS + NROWS) / 4 * 32 / 256, 256>>>(img, text);
    gemm_kernel<<<dim3(NBX, NBY), GEMM_THREADS, SMEM_TOTAL>>>();
    reduce_bi_kernel<<<B_SZ / 8, 256>>>();
    final_kernel<<<1, 32>>>(out);
}